// round 12
// baseline (speedup 1.0000x reference)
#include <cuda_runtime.h>

#define D      1024
#define NCOL   20000
#define TWO_M  512
#define DM1    1023
#define BLK    128
#define NBLK   157
#define FETA   1e-5f
#define EPS    (2.0f * FETA)
#define NIT    4
#define NSEG   8
#define SEGW   20
#define BIGSM  (BLK * BLK * (int)sizeof(float))   // 65536 B (S tile)

// packed dual-fp32 helpers (sm_103a f32x2 pipe)
#define PACK2(d, x, y)  asm("mov.b64 %0, {%1, %2};" : "=l"(d) : "f"(x), "f"(y))
#define FMA2(acc, a, b) asm("fma.rn.f32x2 %0, %1, %2, %0;" : "+l"(acc) : "l"(a), "l"(b))

// ---------------- device globals (no allocation allowed) ----------------
__device__ __align__(16) float g_Spart[2][(size_t)NBLK * BLK * BLK];  // K-half partials
__device__ __align__(16) float g_uh[2][2][NBLK][D];   // [slot][chain][blk][row]
__device__ __align__(16) float g_W[2][2][NSEG][D];    // [slot][chain][seg][row]
__device__ float g_pzh[2][NBLK];
__device__ float g_Wz[2][NSEG];
__device__ __align__(16) float g_y[2][NBLK * BLK];
__device__ float g_x0[D];
__device__ float g_T0, g_q0;

// ---------------- init: x0 gather, q0 = w1.x0, zero T0 ----------------
__global__ __launch_bounds__(1024) void init_kernel(const float* __restrict__ At,
                                                    const float* __restrict__ w1) {
    __shared__ float red[32];
    int tid = threadIdx.x;
    float x0 = At[(size_t)tid * NCOL];
    g_x0[tid] = x0;
    float p = w1[tid] * x0;
    #pragma unroll
    for (int o = 16; o; o >>= 1) p += __shfl_down_sync(0xffffffffu, p, o);
    if ((tid & 31) == 0) red[tid >> 5] = p;
    __syncthreads();
    if (tid < 32) {
        float q = red[tid];
        #pragma unroll
        for (int o = 16; o; o >>= 1) q += __shfl_down_sync(0xffffffffu, q, o);
        if (tid == 0) { g_q0 = q; g_T0 = 0.0f; }
    }
}

// ---------------- T0 = ||W2_init @ a_0||^2 ; grid 16 ----------------
__global__ __launch_bounds__(256) void t0_kernel(const float* __restrict__ W2) {
    int wid = threadIdx.x >> 5, lane = threadIdx.x & 31;
    float acc = 0.0f;
    #pragma unroll
    for (int rr = 0; rr < 4; rr++) {
        int m = blockIdx.x * 32 + wid * 4 + rr;
        const float* row = W2 + (size_t)m * DM1;
        float p = 0.0f;
        for (int c = lane; c < DM1; c += 32) p = fmaf(row[c], g_x0[c], p);
        #pragma unroll
        for (int o = 16; o; o >>= 1) p += __shfl_down_sync(0xffffffffu, p, o);
        if (lane == 0) acc = fmaf(p, p, acc);
    }
    if (lane == 0) atomicAdd(&g_T0, acc);
}

// ---------------- copy b into out[N..2N) ----------------
__global__ void copyb_kernel(const float* __restrict__ b, float* __restrict__ out) {
    int i = blockIdx.x * blockDim.x + threadIdx.x;
    if (i < NCOL) out[NCOL + i] = b[i];
}

// ---------------- zero iteration state (both parities) ----------------
__global__ void zero_state_kernel() {
    int idx = blockIdx.x * blockDim.x + threadIdx.x;
    int stride = gridDim.x * blockDim.x;
    float* u = &g_uh[0][0][0][0];
    for (int i = idx; i < 2 * 2 * NBLK * D; i += stride) u[i] = 0.0f;
    float* w = &g_W[0][0][0][0];
    for (int i = idx; i < 2 * 2 * NSEG * D; i += stride) w[i] = 0.0f;
    float* y = &g_y[0][0];
    for (int i = idx; i < 2 * NBLK * BLK; i += stride) y[i] = 0.0f;
    if (idx < 2 * NBLK) (&g_pzh[0][0])[idx] = 0.0f;
    if (idx < 2 * NSEG) (&g_Wz[0][0])[idx] = 0.0f;
}

// ---------------- diag Gram partials; grid (157,2), 256 thr, 8x8 tiles ----------------
// f32x2 packed-FMA inner loop: each 64-bit acc holds (S[i][2j2], S[i][2j2+1]);
// chains are bit-identical to the scalar-FFMA version.
__global__ __launch_bounds__(256) void gram_kernel(const float* __restrict__ At) {
    __shared__ float sh[32][BLK];
    int k = blockIdx.x, s = k * BLK, kh = blockIdx.y, tid = threadIdx.x;
    int ty = tid >> 4, tx = tid & 15;

    unsigned long long acc2[8][4];
    #pragma unroll
    for (int i = 0; i < 8; i++)
        #pragma unroll
        for (int j = 0; j < 4; j++) acc2[i][j] = 0ull;

    for (int kt = 0; kt < 16; kt++) {
        int r0 = kh * 512 + kt * 32;
        #pragma unroll
        for (int i = 0; i < 4; i++) {
            int f = tid + 256 * i;
            int r = f >> 5;
            int c4 = (f & 31) * 4;
            float4 v = make_float4(0.f, 0.f, 0.f, 0.f);
            if (s + c4 + 3 < NCOL)
                v = *(const float4*)(At + (size_t)(r0 + r) * NCOL + s + c4);
            *(float4*)&sh[r][c4] = v;
        }
        __syncthreads();
        #pragma unroll 4
        for (int r2 = 0; r2 < 32; r2++) {
            float4 a4 = *(const float4*)&sh[r2][8 * ty];
            float4 a5 = *(const float4*)&sh[r2][8 * ty + 4];
            float4 b4 = *(const float4*)&sh[r2][8 * tx];
            float4 b5 = *(const float4*)&sh[r2][8 * tx + 4];
            float av[8] = {a4.x,a4.y,a4.z,a4.w,a5.x,a5.y,a5.z,a5.w};
            unsigned long long bp[4];
            PACK2(bp[0], b4.x, b4.y);
            PACK2(bp[1], b4.z, b4.w);
            PACK2(bp[2], b5.x, b5.y);
            PACK2(bp[3], b5.z, b5.w);
            #pragma unroll
            for (int i = 0; i < 8; i++) {
                unsigned long long ad;
                PACK2(ad, av[i], av[i]);
                FMA2(acc2[i][0], ad, bp[0]);
                FMA2(acc2[i][1], ad, bp[1]);
                FMA2(acc2[i][2], ad, bp[2]);
                FMA2(acc2[i][3], ad, bp[3]);
            }
        }
        __syncthreads();
    }
    float* Sk = g_Spart[kh] + (size_t)k * BLK * BLK;
    #pragma unroll
    for (int i = 0; i < 8; i++) {
        unsigned long long* dst =
            (unsigned long long*)&Sk[(8 * ty + i) * BLK + 8 * tx];
        #pragma unroll
        for (int j = 0; j < 4; j++) dst[j] = acc2[i][j];   // lo float at lower addr
    }
}

// ---------------- one fused Jacobi sweep: 157 CTAs, all blocks parallel ----------------
// parity p: reads W[p], u[p^1], pz[p], Wz[p]; writes u[p], pz[p], W[p^1], Wz[p^1]
// first=1: y==0 state -> skip prefix-build / phase A / S-stage / local matvec
__global__ __launch_bounds__(512) void big_kernel(const float* __restrict__ At,
                                                  const float* __restrict__ b,
                                                  float* __restrict__ out,
                                                  int p, int first, int last) {
    extern __shared__ float dsm[];                 // S tile (128x128)
    __shared__ float Ucm[D], Usm[D];
    __shared__ float pAc[16][BLK], pAs[16][BLK];
    __shared__ float plc[4][BLK], pls[4][BLK];
    __shared__ float yco[BLK], yso[BLK], ycn[BLK], ysn[BLK];
    __shared__ float zz[BLK], bb[BLK], tq[BLK], pref[BLK];
    __shared__ float sPz;

    const int tid = threadIdx.x;
    const int w = tid >> 5, lane = tid & 31;
    const int k = blockIdx.x;
    const int s = k * BLK;
    const int n = (NCOL - s < BLK) ? (NCOL - s) : BLK;
    const int seg = k / SEGW;
    const int segbase = seg * SEGW;
    const int pr = p ^ 1;

    if (tid < BLK) {
        zz[tid] = (tid < n) ? At[(size_t)DM1 * NCOL + s + tid] : 0.f;
        bb[tid] = (tid < n) ? b[s + tid] : 0.f;
    }

    if (!first) {
        // ---- build exclusive-prefix coupling vectors (float4 path) ----
        {
            const int chain = tid >> 8;
            const int slot = tid & 255;
            const float4* Wp = (const float4*)&g_W[p][chain][0][0];
            const float4* up = (const float4*)&g_uh[pr][chain][0][0];
            float4 acc = make_float4(0.f, 0.f, 0.f, 0.f);
            #pragma unroll 2
            for (int s2 = 0; s2 < seg; s2++) {
                float4 v = Wp[s2 * 256 + slot];
                acc.x += v.x; acc.y += v.y; acc.z += v.z; acc.w += v.w;
            }
            #pragma unroll 4
            for (int k2 = segbase; k2 < k; k2++) {
                float4 v = up[k2 * 256 + slot];
                acc.x += v.x; acc.y += v.y; acc.z += v.z; acc.w += v.w;
            }
            float4* dst = (float4*)(chain ? Usm : Ucm);
            dst[slot] = acc;
        }
        if (tid == 0) {
            float a = 0.f;
            for (int s2 = 0; s2 < seg; s2++) a += g_Wz[p][s2];
            for (int k2 = segbase; k2 < k; k2++) a += g_pzh[pr][k2];
            sPz = a;
        }
        if (tid < BLK) {
            yco[tid] = g_y[0][k * BLK + tid];
            yso[tid] = g_y[1][k * BLK + tid];
        }
        __syncthreads();

        // ---- Phase A: coupling dots (x_i . U), direct coalesced loads ----
        {
            const int colb = lane * 4;
            float4 vcA = make_float4(0.f,0.f,0.f,0.f), vsA = make_float4(0.f,0.f,0.f,0.f);
            if (colb < n) {
                const float* Xw = At + (size_t)(w * 64) * NCOL + s + colb;
                #pragma unroll 8
                for (int r = 0; r < 64; r++) {
                    float uc = Ucm[w * 64 + r], us = Usm[w * 64 + r];
                    float4 xv = *(const float4*)(Xw + (size_t)r * NCOL);
                    vcA.x = fmaf(uc, xv.x, vcA.x); vcA.y = fmaf(uc, xv.y, vcA.y);
                    vcA.z = fmaf(uc, xv.z, vcA.z); vcA.w = fmaf(uc, xv.w, vcA.w);
                    vsA.x = fmaf(us, xv.x, vsA.x); vsA.y = fmaf(us, xv.y, vsA.y);
                    vsA.z = fmaf(us, xv.z, vsA.z); vsA.w = fmaf(us, xv.w, vsA.w);
                }
            }
            *(float4*)&pAc[w][colb] = vcA;
            *(float4*)&pAs[w][colb] = vsA;
        }

        // ---- stage local Gram S = sum of K-half partials ----
        {
            const float4* Sg0 = (const float4*)(g_Spart[0] + (size_t)k * BLK * BLK);
            const float4* Sg1 = (const float4*)(g_Spart[1] + (size_t)k * BLK * BLK);
            float4* Ss = (float4*)dsm;
            #pragma unroll
            for (int ii = 0; ii < 8; ii++) {
                float4 a = Sg0[tid + 512 * ii];
                float4 c = Sg1[tid + 512 * ii];
                Ss[tid + 512 * ii] = make_float4(a.x + c.x, a.y + c.y, a.z + c.z, a.w + c.w);
            }
        }
        if (tid < BLK) tq[tid] = zz[tid] * yco[tid];
        __syncthreads();

        // ---- local strict-lower matvecs (both chains) ----
        {
            const int qq = tid >> 7, i = tid & 127, jb = qq * 32;
            float lc = 0.f, ls = 0.f;
            #pragma unroll 8
            for (int j2 = 0; j2 < 32; j2++) {
                int j = jb + j2;
                if (j < i) {
                    float sv = dsm[j * BLK + i];
                    lc = fmaf(sv, yco[j], lc);
                    ls = fmaf(sv, yso[j], ls);
                }
            }
            plc[qq][i] = lc; pls[qq][i] = ls;
        }
        if (tid < 32) {          // exclusive prefix of z*yc_old
            float v0 = tq[4*tid], v1 = tq[4*tid+1], v2 = tq[4*tid+2], v3 = tq[4*tid+3];
            float i0 = v0, i1 = i0 + v1, i2 = i1 + v2, i3 = i2 + v3;
            float run = i3;
            #pragma unroll
            for (int o = 1; o < 32; o <<= 1) {
                float u2 = __shfl_up_sync(0xffffffffu, run, o);
                if ((int)tid >= o) run += u2;
            }
            float ex = run - i3;
            pref[4*tid] = ex; pref[4*tid+1] = ex + i0;
            pref[4*tid+2] = ex + i1; pref[4*tid+3] = ex + i2;
        }
        __syncthreads();
    }

    // ---- combine + Jacobi update ----
    if (tid < BLK) {
        const int i = tid;
        float cc = 0.f, cs = 0.f, lc = 0.f, ls = 0.f, zp = 0.f;
        if (!first) {
            #pragma unroll
            for (int pp = 0; pp < 16; pp++) { cc += pAc[pp][i]; cs += pAs[pp][i]; }
            lc = plc[0][i] + plc[1][i] + plc[2][i] + plc[3][i];
            ls = pls[0][i] + pls[1][i] + pls[2][i] + pls[3][i];
            zp = sPz + pref[i];
        }
        float rc = (s + i == 0) ? 1.0f : 0.0f;
        float cnew = rc - EPS * (cc + lc - zz[i] * zp);
        float rs = fmaf(2.0f * g_T0, cnew * cnew, -2.0f * bb[i]);
        if (s + i == 0) rs += 2.0f * g_q0;
        float snew = rs - EPS * (cs + ls);
        ycn[i] = cnew; ysn[i] = snew;
        g_y[0][k * BLK + i] = cnew;
        g_y[1][k * BLK + i] = snew;
        if (last && i < n) out[s + i] = fmaf(0.5f, snew, bb[i]);
        tq[i] = zz[i] * cnew;
    }
    __syncthreads();

    if (last) return;

    if (tid < 32) {           // pz block sum of z*cnew, publish + segment delta
        float v = tq[4*tid] + tq[4*tid+1] + tq[4*tid+2] + tq[4*tid+3];
        #pragma unroll
        for (int o = 16; o; o >>= 1) v += __shfl_down_sync(0xffffffffu, v, o);
        if (tid == 0) {
            float old = g_pzh[p][k];
            g_pzh[p][k] = v;
            atomicAdd(&g_Wz[pr][seg], v - old);
        }
    }

    // ---- Phase U: u = X @ ynew; pass pairs fused for MLP 8 ----
    {
        const int g8 = lane >> 3, gl = lane & 7;     // 4 groups of 8 lanes
        for (int m = 0; m < 8; m++) {
            int r0 = w * 64 + m * 8 + g8;
            int r1 = r0 + 4;
            const float* rp0 = At + (size_t)r0 * NCOL + s;
            const float* rp1 = At + (size_t)r1 * NCOL + s;
            float uc0 = 0.f, us0 = 0.f, uc1 = 0.f, us1 = 0.f;
            #pragma unroll
            for (int it = 0; it < 4; it++) {
                int col = it * 32 + gl * 4;
                if (col < n) {
                    float4 xa = *(const float4*)(rp0 + col);
                    float4 xb = *(const float4*)(rp1 + col);
                    float y0 = ycn[col], y1 = ycn[col+1], y2 = ycn[col+2], y3 = ycn[col+3];
                    float t0 = ysn[col], t1 = ysn[col+1], t2 = ysn[col+2], t3 = ysn[col+3];
                    uc0 = fmaf(xa.x,y0,fmaf(xa.y,y1,fmaf(xa.z,y2,fmaf(xa.w,y3,uc0))));
                    us0 = fmaf(xa.x,t0,fmaf(xa.y,t1,fmaf(xa.z,t2,fmaf(xa.w,t3,us0))));
                    uc1 = fmaf(xb.x,y0,fmaf(xb.y,y1,fmaf(xb.z,y2,fmaf(xb.w,y3,uc1))));
                    us1 = fmaf(xb.x,t0,fmaf(xb.y,t1,fmaf(xb.z,t2,fmaf(xb.w,t3,us1))));
                }
            }
            #pragma unroll
            for (int o = 4; o; o >>= 1) {
                uc0 += __shfl_down_sync(0xffffffffu, uc0, o, 8);
                us0 += __shfl_down_sync(0xffffffffu, us0, o, 8);
                uc1 += __shfl_down_sync(0xffffffffu, uc1, o, 8);
                us1 += __shfl_down_sync(0xffffffffu, us1, o, 8);
            }
            if (gl == 0) {
                float oc0 = g_uh[p][0][k][r0], os0 = g_uh[p][1][k][r0];
                float oc1 = g_uh[p][0][k][r1], os1 = g_uh[p][1][k][r1];
                g_uh[p][0][k][r0] = uc0; g_uh[p][1][k][r0] = us0;
                g_uh[p][0][k][r1] = uc1; g_uh[p][1][k][r1] = us1;
                atomicAdd(&g_W[pr][0][seg][r0], uc0 - oc0);
                atomicAdd(&g_W[pr][1][seg][r0], us0 - os0);
                atomicAdd(&g_W[pr][0][seg][r1], uc1 - oc1);
                atomicAdd(&g_W[pr][1][seg][r1], us1 - os1);
            }
        }
    }
}

// ---------------- launch ----------------
extern "C" void kernel_launch(void* const* d_in, const int* in_sizes, int n_in,
                              void* d_out, int out_size) {
    const float* At = (const float*)d_in[0];
    const float* b  = (const float*)d_in[1];
    const float* w1 = (const float*)d_in[2];
    const float* W2 = (const float*)d_in[3];
    float* out = (float*)d_out;

    cudaFuncSetAttribute(big_kernel, cudaFuncAttributeMaxDynamicSharedMemorySize, BIGSM);

    init_kernel<<<1, 1024>>>(At, w1);
    t0_kernel<<<16, 256>>>(W2);
    if (out_size >= 2 * NCOL)
        copyb_kernel<<<(NCOL + 255) / 256, 256>>>(b, out);
    gram_kernel<<<dim3(NBLK, 2), 256>>>(At);
    zero_state_kernel<<<160, 1024>>>();

    for (int t = 0; t < NIT; t++)
        big_kernel<<<NBLK, 512, BIGSM>>>(At, b, out, t & 1,
                                         t == 0 ? 1 : 0, t == NIT - 1 ? 1 : 0);
}

// round 14
// speedup vs baseline: 1.0441x; 1.0441x over previous
#include <cuda_runtime.h>
#include <cuda_bf16.h>
#include <cstdint>

#define D      1024
#define NCOL   20000
#define TWO_M  512
#define DM1    1023
#define BLK    128
#define NBLK   157
#define FETA   1e-5f
#define EPS    (2.0f * FETA)
#define NIT    4
#define NSEG   8
#define SEGW   20
#define BIGSM  (BLK * BLK * (int)sizeof(float))   // 65536 B (S tile)

// gram_mma smem: fp32 staging [64][132] (33792 B) + Xt_hi [128][33 w] (16896 B) + Xt_lo (16896 B)
#define XS_F32 132
#define XT_S   33
#define GRAM_STG_B  (64 * XS_F32 * 4)             // 33792
#define GRAM_XHI_B  (BLK * XT_S * 4)              // 16896
#define GRAMSM (GRAM_STG_B + 2 * GRAM_XHI_B)      // 67584

// ---------------- device globals (no allocation allowed) ----------------
__device__ __align__(16) float g_S[(size_t)NBLK * BLK * BLK];   // 10.3 MB
__device__ __align__(16) float g_uh[2][2][NBLK][D];   // [slot][chain][blk][row]
__device__ __align__(16) float g_W[2][2][NSEG][D];    // [slot][chain][seg][row]
__device__ float g_pzh[2][NBLK];
__device__ float g_Wz[2][NSEG];
__device__ __align__(16) float g_y[2][NBLK * BLK];
__device__ float g_x0[D];
__device__ float g_T0, g_q0;

// ---------------- init: x0 gather, q0 = w1.x0, zero T0 ----------------
__global__ __launch_bounds__(1024) void init_kernel(const float* __restrict__ At,
                                                    const float* __restrict__ w1) {
    __shared__ float red[32];
    int tid = threadIdx.x;
    float x0 = At[(size_t)tid * NCOL];
    g_x0[tid] = x0;
    float p = w1[tid] * x0;
    #pragma unroll
    for (int o = 16; o; o >>= 1) p += __shfl_down_sync(0xffffffffu, p, o);
    if ((tid & 31) == 0) red[tid >> 5] = p;
    __syncthreads();
    if (tid < 32) {
        float q = red[tid];
        #pragma unroll
        for (int o = 16; o; o >>= 1) q += __shfl_down_sync(0xffffffffu, q, o);
        if (tid == 0) { g_q0 = q; g_T0 = 0.0f; }
    }
}

// ---------------- T0 = ||W2_init @ a_0||^2 ; grid 16 ----------------
__global__ __launch_bounds__(256) void t0_kernel(const float* __restrict__ W2) {
    int wid = threadIdx.x >> 5, lane = threadIdx.x & 31;
    float acc = 0.0f;
    #pragma unroll
    for (int rr = 0; rr < 4; rr++) {
        int m = blockIdx.x * 32 + wid * 4 + rr;
        const float* row = W2 + (size_t)m * DM1;
        float p = 0.0f;
        for (int c = lane; c < DM1; c += 32) p = fmaf(row[c], g_x0[c], p);
        #pragma unroll
        for (int o = 16; o; o >>= 1) p += __shfl_down_sync(0xffffffffu, p, o);
        if (lane == 0) acc = fmaf(p, p, acc);
    }
    if (lane == 0) atomicAdd(&g_T0, acc);
}

// ---------------- copy b into out[N..2N) ----------------
__global__ void copyb_kernel(const float* __restrict__ b, float* __restrict__ out) {
    int i = blockIdx.x * blockDim.x + threadIdx.x;
    if (i < NCOL) out[NCOL + i] = b[i];
}

// ---------------- zero iteration state (both parities) ----------------
__global__ void zero_state_kernel() {
    int idx = blockIdx.x * blockDim.x + threadIdx.x;
    int stride = gridDim.x * blockDim.x;
    float* u = &g_uh[0][0][0][0];
    for (int i = idx; i < 2 * 2 * NBLK * D; i += stride) u[i] = 0.0f;
    float* w = &g_W[0][0][0][0];
    for (int i = idx; i < 2 * 2 * NSEG * D; i += stride) w[i] = 0.0f;
    float* y = &g_y[0][0];
    for (int i = idx; i < 2 * NBLK * BLK; i += stride) y[i] = 0.0f;
    if (idx < 2 * NBLK) (&g_pzh[0][0])[idx] = 0.0f;
    if (idx < 2 * NSEG) (&g_Wz[0][0])[idx] = 0.0f;
}

// ---------------- tensor-core diag Gram via mma.sync bf16 split-precision ----------------
// grid 157, 256 thr (8 warps). Warp w owns C rows [16w,16w+16); 16 n-tiles of 8.
// S = Xhi^T Xhi + Xhi^T Xlo + Xlo^T Xhi accumulated in fp32 (lo*lo dropped, ~2^-16 rel).
__global__ __launch_bounds__(256) void gram_mma_kernel(const float* __restrict__ At) {
    extern __shared__ char gsm[];
    float*    stg = (float*)gsm;                                 // [64][XS_F32]
    uint32_t* xhi = (uint32_t*)(gsm + GRAM_STG_B);               // [128][XT_S] packed bf16 pairs
    uint32_t* xlo = (uint32_t*)(gsm + GRAM_STG_B + GRAM_XHI_B);

    const int k = blockIdx.x, s = k * BLK, tid = threadIdx.x;
    const int w = tid >> 5, lane = tid & 31;
    const int g = lane >> 2, t = lane & 3;

    float acc[16][4];
    #pragma unroll
    for (int tj = 0; tj < 16; tj++)
        #pragma unroll
        for (int q = 0; q < 4; q++) acc[tj][q] = 0.0f;

    for (int ch = 0; ch < 16; ch++) {
        const int r0 = ch * 64;
        // ---- stage 64 x 128 fp32 (coalesced LDG) ----
        #pragma unroll
        for (int j = 0; j < 8; j++) {
            int e = tid + 256 * j;
            int r = e >> 5, c4 = (e & 31) * 4;
            float4 v = make_float4(0.f, 0.f, 0.f, 0.f);
            if (s + c4 + 3 < NCOL)
                v = *(const float4*)(At + (size_t)(r0 + r) * NCOL + s + c4);
            *(float4*)&stg[r * XS_F32 + c4] = v;
        }
        __syncthreads();
        // ---- transpose + split-convert into Xt (packed pairs along K) ----
        {
            const int i = tid & 127;
            const int half = tid >> 7;
            #pragma unroll
            for (int vv = 0; vv < 16; vv++) {
                int rp = vv * 2 + half;                 // 0..31 (pair of K-rows)
                float x0 = stg[(2 * rp) * XS_F32 + i];
                float x1 = stg[(2 * rp + 1) * XS_F32 + i];
                __nv_bfloat16 h0 = __float2bfloat16(x0);
                __nv_bfloat16 h1 = __float2bfloat16(x1);
                __nv_bfloat16 l0 = __float2bfloat16(x0 - __bfloat162float(h0));
                __nv_bfloat16 l1 = __float2bfloat16(x1 - __bfloat162float(h1));
                xhi[i * XT_S + rp] = (uint32_t)__bfloat16_as_ushort(h0)
                                   | ((uint32_t)__bfloat16_as_ushort(h1) << 16);
                xlo[i * XT_S + rp] = (uint32_t)__bfloat16_as_ushort(l0)
                                   | ((uint32_t)__bfloat16_as_ushort(l1) << 16);
            }
        }
        __syncthreads();
        // ---- 4 k-steps of m16n8k16 over this chunk ----
        #pragma unroll
        for (int ks = 0; ks < 4; ks++) {
            const int kb = ks * 8;
            uint32_t ah[4], al[4];
            ah[0] = xhi[(16 * w + g) * XT_S + kb + t];
            ah[1] = xhi[(16 * w + 8 + g) * XT_S + kb + t];
            ah[2] = xhi[(16 * w + g) * XT_S + kb + 4 + t];
            ah[3] = xhi[(16 * w + 8 + g) * XT_S + kb + 4 + t];
            al[0] = xlo[(16 * w + g) * XT_S + kb + t];
            al[1] = xlo[(16 * w + 8 + g) * XT_S + kb + t];
            al[2] = xlo[(16 * w + g) * XT_S + kb + 4 + t];
            al[3] = xlo[(16 * w + 8 + g) * XT_S + kb + 4 + t];
            #pragma unroll
            for (int tj = 0; tj < 16; tj++) {
                uint32_t bh0 = xhi[(8 * tj + g) * XT_S + kb + t];
                uint32_t bh1 = xhi[(8 * tj + g) * XT_S + kb + 4 + t];
                uint32_t bl0 = xlo[(8 * tj + g) * XT_S + kb + t];
                uint32_t bl1 = xlo[(8 * tj + g) * XT_S + kb + 4 + t];
                asm volatile(
                    "mma.sync.aligned.m16n8k16.row.col.f32.bf16.bf16.f32 "
                    "{%0,%1,%2,%3}, {%4,%5,%6,%7}, {%8,%9}, {%0,%1,%2,%3};"
                    : "+f"(acc[tj][0]), "+f"(acc[tj][1]), "+f"(acc[tj][2]), "+f"(acc[tj][3])
                    : "r"(ah[0]), "r"(ah[1]), "r"(ah[2]), "r"(ah[3]), "r"(bh0), "r"(bh1));
                asm volatile(
                    "mma.sync.aligned.m16n8k16.row.col.f32.bf16.bf16.f32 "
                    "{%0,%1,%2,%3}, {%4,%5,%6,%7}, {%8,%9}, {%0,%1,%2,%3};"
                    : "+f"(acc[tj][0]), "+f"(acc[tj][1]), "+f"(acc[tj][2]), "+f"(acc[tj][3])
                    : "r"(ah[0]), "r"(ah[1]), "r"(ah[2]), "r"(ah[3]), "r"(bl0), "r"(bl1));
                asm volatile(
                    "mma.sync.aligned.m16n8k16.row.col.f32.bf16.bf16.f32 "
                    "{%0,%1,%2,%3}, {%4,%5,%6,%7}, {%8,%9}, {%0,%1,%2,%3};"
                    : "+f"(acc[tj][0]), "+f"(acc[tj][1]), "+f"(acc[tj][2]), "+f"(acc[tj][3])
                    : "r"(al[0]), "r"(al[1]), "r"(al[2]), "r"(al[3]), "r"(bh0), "r"(bh1));
            }
        }
        __syncthreads();
    }
    // ---- writeout (c0:(g,2t) c1:(g,2t+1) c2:(g+8,2t) c3:(g+8,2t+1)) ----
    float* Sk = g_S + (size_t)k * BLK * BLK;
    #pragma unroll
    for (int tj = 0; tj < 16; tj++) {
        int row = 16 * w + g, col = 8 * tj + 2 * t;
        Sk[row * BLK + col]           = acc[tj][0];
        Sk[row * BLK + col + 1]       = acc[tj][1];
        Sk[(row + 8) * BLK + col]     = acc[tj][2];
        Sk[(row + 8) * BLK + col + 1] = acc[tj][3];
    }
}

// ---------------- one fused Jacobi sweep: 157 CTAs, all blocks parallel ----------------
__global__ __launch_bounds__(512) void big_kernel(const float* __restrict__ At,
                                                  const float* __restrict__ b,
                                                  float* __restrict__ out,
                                                  int p, int first, int last) {
    extern __shared__ float dsm[];                 // S tile (128x128)
    __shared__ float Ucm[D], Usm[D];
    __shared__ float pAc[16][BLK], pAs[16][BLK];
    __shared__ float plc[4][BLK], pls[4][BLK];
    __shared__ float yco[BLK], yso[BLK], ycn[BLK], ysn[BLK];
    __shared__ float zz[BLK], bb[BLK], tq[BLK], pref[BLK];
    __shared__ float sPz;

    const int tid = threadIdx.x;
    const int w = tid >> 5, lane = tid & 31;
    const int k = blockIdx.x;
    const int s = k * BLK;
    const int n = (NCOL - s < BLK) ? (NCOL - s) : BLK;
    const int seg = k / SEGW;
    const int segbase = seg * SEGW;
    const int pr = p ^ 1;

    if (tid < BLK) {
        zz[tid] = (tid < n) ? At[(size_t)DM1 * NCOL + s + tid] : 0.f;
        bb[tid] = (tid < n) ? b[s + tid] : 0.f;
    }

    if (!first) {
        {
            const int chain = tid >> 8;
            const int slot = tid & 255;
            const float4* Wp = (const float4*)&g_W[p][chain][0][0];
            const float4* up = (const float4*)&g_uh[pr][chain][0][0];
            float4 acc = make_float4(0.f, 0.f, 0.f, 0.f);
            #pragma unroll 2
            for (int s2 = 0; s2 < seg; s2++) {
                float4 v = Wp[s2 * 256 + slot];
                acc.x += v.x; acc.y += v.y; acc.z += v.z; acc.w += v.w;
            }
            #pragma unroll 4
            for (int k2 = segbase; k2 < k; k2++) {
                float4 v = up[k2 * 256 + slot];
                acc.x += v.x; acc.y += v.y; acc.z += v.z; acc.w += v.w;
            }
            float4* dst = (float4*)(chain ? Usm : Ucm);
            dst[slot] = acc;
        }
        if (tid == 0) {
            float a = 0.f;
            for (int s2 = 0; s2 < seg; s2++) a += g_Wz[p][s2];
            for (int k2 = segbase; k2 < k; k2++) a += g_pzh[pr][k2];
            sPz = a;
        }
        if (tid < BLK) {
            yco[tid] = g_y[0][k * BLK + tid];
            yso[tid] = g_y[1][k * BLK + tid];
        }
        __syncthreads();

        // ---- Phase A: coupling dots (x_i . U), direct coalesced loads ----
        {
            const int colb = lane * 4;
            float4 vcA = make_float4(0.f,0.f,0.f,0.f), vsA = make_float4(0.f,0.f,0.f,0.f);
            if (colb < n) {
                const float* Xw = At + (size_t)(w * 64) * NCOL + s + colb;
                #pragma unroll 8
                for (int r = 0; r < 64; r++) {
                    float uc = Ucm[w * 64 + r], us = Usm[w * 64 + r];
                    float4 xv = *(const float4*)(Xw + (size_t)r * NCOL);
                    vcA.x = fmaf(uc, xv.x, vcA.x); vcA.y = fmaf(uc, xv.y, vcA.y);
                    vcA.z = fmaf(uc, xv.z, vcA.z); vcA.w = fmaf(uc, xv.w, vcA.w);
                    vsA.x = fmaf(us, xv.x, vsA.x); vsA.y = fmaf(us, xv.y, vsA.y);
                    vsA.z = fmaf(us, xv.z, vsA.z); vsA.w = fmaf(us, xv.w, vsA.w);
                }
            }
            *(float4*)&pAc[w][colb] = vcA;
            *(float4*)&pAs[w][colb] = vsA;
        }

        // ---- stage local Gram S ----
        {
            const float4* Sg = (const float4*)(g_S + (size_t)k * BLK * BLK);
            float4* Ss = (float4*)dsm;
            #pragma unroll
            for (int ii = 0; ii < 8; ii++) Ss[tid + 512 * ii] = Sg[tid + 512 * ii];
        }
        if (tid < BLK) tq[tid] = zz[tid] * yco[tid];
        __syncthreads();

        // ---- local strict-lower matvecs (both chains) ----
        {
            const int qq = tid >> 7, i = tid & 127, jb = qq * 32;
            float lc = 0.f, ls = 0.f;
            #pragma unroll 8
            for (int j2 = 0; j2 < 32; j2++) {
                int j = jb + j2;
                if (j < i) {
                    float sv = dsm[j * BLK + i];
                    lc = fmaf(sv, yco[j], lc);
                    ls = fmaf(sv, yso[j], ls);
                }
            }
            plc[qq][i] = lc; pls[qq][i] = ls;
        }
        if (tid < 32) {          // exclusive prefix of z*yc_old
            float v0 = tq[4*tid], v1 = tq[4*tid+1], v2 = tq[4*tid+2], v3 = tq[4*tid+3];
            float i0 = v0, i1 = i0 + v1, i2 = i1 + v2, i3 = i2 + v3;
            float run = i3;
            #pragma unroll
            for (int o = 1; o < 32; o <<= 1) {
                float u2 = __shfl_up_sync(0xffffffffu, run, o);
                if ((int)tid >= o) run += u2;
            }
            float ex = run - i3;
            pref[4*tid] = ex; pref[4*tid+1] = ex + i0;
            pref[4*tid+2] = ex + i1; pref[4*tid+3] = ex + i2;
        }
        __syncthreads();
    }

    // ---- combine + Jacobi update ----
    if (tid < BLK) {
        const int i = tid;
        float cc = 0.f, cs = 0.f, lc = 0.f, ls = 0.f, zp = 0.f;
        if (!first) {
            #pragma unroll
            for (int pp = 0; pp < 16; pp++) { cc += pAc[pp][i]; cs += pAs[pp][i]; }
            lc = plc[0][i] + plc[1][i] + plc[2][i] + plc[3][i];
            ls = pls[0][i] + pls[1][i] + pls[2][i] + pls[3][i];
            zp = sPz + pref[i];
        }
        float rc = (s + i == 0) ? 1.0f : 0.0f;
        float cnew = rc - EPS * (cc + lc - zz[i] * zp);
        float rs = fmaf(2.0f * g_T0, cnew * cnew, -2.0f * bb[i]);
        if (s + i == 0) rs += 2.0f * g_q0;
        float snew = rs - EPS * (cs + ls);
        ycn[i] = cnew; ysn[i] = snew;
        g_y[0][k * BLK + i] = cnew;
        g_y[1][k * BLK + i] = snew;
        if (last && i < n) out[s + i] = fmaf(0.5f, snew, bb[i]);
        tq[i] = zz[i] * cnew;
    }
    __syncthreads();

    if (last) return;

    if (tid < 32) {           // pz block sum of z*cnew, publish + segment delta
        float v = tq[4*tid] + tq[4*tid+1] + tq[4*tid+2] + tq[4*tid+3];
        #pragma unroll
        for (int o = 16; o; o >>= 1) v += __shfl_down_sync(0xffffffffu, v, o);
        if (tid == 0) {
            float old = g_pzh[p][k];
            g_pzh[p][k] = v;
            atomicAdd(&g_Wz[pr][seg], v - old);
        }
    }

    // ---- Phase U: u = X @ ynew; pass pairs fused for MLP 8 ----
    {
        const int g8 = lane >> 3, gl = lane & 7;
        for (int m = 0; m < 8; m++) {
            int r0 = w * 64 + m * 8 + g8;
            int r1 = r0 + 4;
            const float* rp0 = At + (size_t)r0 * NCOL + s;
            const float* rp1 = At + (size_t)r1 * NCOL + s;
            float uc0 = 0.f, us0 = 0.f, uc1 = 0.f, us1 = 0.f;
            #pragma unroll
            for (int it = 0; it < 4; it++) {
                int col = it * 32 + gl * 4;
                if (col < n) {
                    float4 xa = *(const float4*)(rp0 + col);
                    float4 xb = *(const float4*)(rp1 + col);
                    float y0 = ycn[col], y1 = ycn[col+1], y2 = ycn[col+2], y3 = ycn[col+3];
                    float t0 = ysn[col], t1 = ysn[col+1], t2 = ysn[col+2], t3 = ysn[col+3];
                    uc0 = fmaf(xa.x,y0,fmaf(xa.y,y1,fmaf(xa.z,y2,fmaf(xa.w,y3,uc0))));
                    us0 = fmaf(xa.x,t0,fmaf(xa.y,t1,fmaf(xa.z,t2,fmaf(xa.w,t3,us0))));
                    uc1 = fmaf(xb.x,y0,fmaf(xb.y,y1,fmaf(xb.z,y2,fmaf(xb.w,y3,uc1))));
                    us1 = fmaf(xb.x,t0,fmaf(xb.y,t1,fmaf(xb.z,t2,fmaf(xb.w,t3,us1))));
                }
            }
            #pragma unroll
            for (int o = 4; o; o >>= 1) {
                uc0 += __shfl_down_sync(0xffffffffu, uc0, o, 8);
                us0 += __shfl_down_sync(0xffffffffu, us0, o, 8);
                uc1 += __shfl_down_sync(0xffffffffu, uc1, o, 8);
                us1 += __shfl_down_sync(0xffffffffu, us1, o, 8);
            }
            if (gl == 0) {
                float oc0 = g_uh[p][0][k][r0], os0 = g_uh[p][1][k][r0];
                float oc1 = g_uh[p][0][k][r1], os1 = g_uh[p][1][k][r1];
                g_uh[p][0][k][r0] = uc0; g_uh[p][1][k][r0] = us0;
                g_uh[p][0][k][r1] = uc1; g_uh[p][1][k][r1] = us1;
                atomicAdd(&g_W[pr][0][seg][r0], uc0 - oc0);
                atomicAdd(&g_W[pr][1][seg][r0], us0 - os0);
                atomicAdd(&g_W[pr][0][seg][r1], uc1 - oc1);
                atomicAdd(&g_W[pr][1][seg][r1], us1 - os1);
            }
        }
    }
}

// ---------------- launch ----------------
extern "C" void kernel_launch(void* const* d_in, const int* in_sizes, int n_in,
                              void* d_out, int out_size) {
    const float* At = (const float*)d_in[0];
    const float* b  = (const float*)d_in[1];
    const float* w1 = (const float*)d_in[2];
    const float* W2 = (const float*)d_in[3];
    float* out = (float*)d_out;

    cudaFuncSetAttribute(big_kernel, cudaFuncAttributeMaxDynamicSharedMemorySize, BIGSM);
    cudaFuncSetAttribute(gram_mma_kernel, cudaFuncAttributeMaxDynamicSharedMemorySize, GRAMSM);

    init_kernel<<<1, 1024>>>(At, w1);
    t0_kernel<<<16, 256>>>(W2);
    if (out_size >= 2 * NCOL)
        copyb_kernel<<<(NCOL + 255) / 256, 256>>>(b, out);
    gram_mma_kernel<<<NBLK, 256, GRAMSM>>>(At);
    zero_state_kernel<<<160, 1024>>>();

    for (int t = 0; t < NIT; t++)
        big_kernel<<<NBLK, 512, BIGSM>>>(At, b, out, t & 1,
                                         t == 0 ? 1 : 0, t == NIT - 1 ? 1 : 0);
}